// round 13
// baseline (speedup 1.0000x reference)
#include <cuda_runtime.h>
#include <cuda_bf16.h>
#include <math.h>
#include <cstdint>

#define BB 32
#define AA 1024
#define FF 128
#define NN (BB*AA)

// ================= scratch =================
__device__ float g_u2[2][FF];
__device__ float g_bk2[2];
__device__ float g_wow[FF];
__device__ float g_num[NN];
__device__ float g_numpart[NN/256];
__device__ float g_ezwe[NN];
__device__ float4 g_xyzq[NN];       // packed (x, y, z, pred_q) written by k2
__device__ float g_partial[BB*16];
__device__ int   g_cnt[BB];
// W1^T / W2^T as bf16, layout Wt[n][k], row stride 136 (272 B): 128*136*2 = 34816 B each
__device__ uint4 g_W1bf4[2176];
__device__ uint4 g_W2bf4[2176];

__device__ __forceinline__ float tanha(float x) {
    float r;
    asm("tanh.approx.f32 %0, %1;" : "=f"(r) : "f"(x));
    return r;
}
__device__ __forceinline__ float fsilu(float x) {   // x*sigmoid(x) = 0.5x(1+tanh(x/2))
    float h = 0.5f * x;
    return fmaf(h, tanha(h), h);
}
__device__ __forceinline__ float rsqa(float x) {    // exactly one MUFU.RSQ
    float r;
    asm("rsqrt.approx.f32 %0, %1;" : "=f"(r) : "f"(x));
    return r;
}
__device__ __forceinline__ uint32_t packbf(float lo, float hi) {
    uint32_t r;
    asm("cvt.rn.satfinite.bf16x2.f32 %0, %1, %2;" : "=r"(r) : "f"(hi), "f"(lo));
    return r;
}
__device__ __forceinline__ uint32_t smem_u32(const void* p) {
    uint32_t a;
    asm("{ .reg .u64 t; cvta.to.shared.u64 t, %1; cvt.u32.u64 %0, t; }" : "=r"(a) : "l"(p));
    return a;
}
__device__ __forceinline__ void ldsm_x4(uint32_t& r0, uint32_t& r1, uint32_t& r2, uint32_t& r3,
                                        uint32_t addr) {
    asm volatile("ldmatrix.sync.aligned.m8n8.x4.shared.b16 {%0,%1,%2,%3}, [%4];"
                 : "=r"(r0), "=r"(r1), "=r"(r2), "=r"(r3) : "r"(addr));
}
__device__ __forceinline__ void mma16816(float* d, const uint32_t* a, uint32_t b0, uint32_t b1) {
    asm volatile("mma.sync.aligned.m16n8k16.row.col.f32.bf16.bf16.f32 "
                 "{%0,%1,%2,%3}, {%4,%5,%6,%7}, {%8,%9}, {%0,%1,%2,%3};"
                 : "+f"(d[0]), "+f"(d[1]), "+f"(d[2]), "+f"(d[3])
                 : "r"(a[0]), "r"(a[1]), "r"(a[2]), "r"(a[3]), "r"(b0), "r"(b1));
}

// ---------------- K0f: fused precompute (weight convert + projected vectors) ----
__global__ void k0f(const float* __restrict__ W1, const float* __restrict__ W2,
                    const float* __restrict__ W_lin, const float* __restrict__ b_lin,
                    const float* __restrict__ kp, const float* __restrict__ km,
                    const float* __restrict__ Wout, const float* __restrict__ w_e) {
    int blk = blockIdx.x, tid = threadIdx.x;
    if (blk < 64) {
        int i = blk * 256 + tid;                 // 0..16383
        int k = i >> 7, n = i & 127;
        int off = n*136 + k;
        ((__nv_bfloat16*)g_W1bf4)[off] = __float2bfloat16(W1[k*FF + n]);
        ((__nv_bfloat16*)g_W2bf4)[off] = __float2bfloat16(W2[k*FF + n]);
        return;
    }
    __shared__ float r0[256], r1[256], r2[256];
    if (blk < 192) {
        int g = blk - 64;
        float a0 = 0.f, a1 = 0.f, a2 = 0.f;
        if (tid < 128) {
            float w = W_lin[g*FF + tid];
            a0 = w * kp[tid];
            a1 = w * km[tid];
            a2 = Wout[g*FF + tid] * w_e[tid];
        }
        r0[tid] = a0; r1[tid] = a1; r2[tid] = a2;
        __syncthreads();
        for (int off = 128; off > 0; off >>= 1) {
            if (tid < off) { r0[tid] += r0[tid+off]; r1[tid] += r1[tid+off]; r2[tid] += r2[tid+off]; }
            __syncthreads();
        }
        if (tid == 0) { g_u2[0][g] = r0[0]; g_u2[1][g] = r1[0]; g_wow[g] = r2[0]; }
        return;
    }
    float a0 = 0.f, a1 = 0.f;
    if (tid < 128) { float bl = b_lin[tid]; a0 = bl * kp[tid]; a1 = bl * km[tid]; }
    r0[tid] = a0; r1[tid] = a1;
    __syncthreads();
    for (int off = 128; off > 0; off >>= 1) {
        if (tid < off) { r0[tid] += r0[tid+off]; r1[tid] += r1[tid+off]; }
        __syncthreads();
    }
    if (tid == 0) { g_bk2[0] = r0[0]; g_bk2[1] = r1[0]; }
}

// ---------------- K1: warp-per-row coalesced dots, one pass over e_z ----------
__global__ void k1_fused(const float* __restrict__ e_z, const float* __restrict__ charge,
                         const float* __restrict__ w_e) {
    __shared__ float s_u[FF];
    __shared__ float s_we[FF];
    __shared__ float s_ws[8];
    int bb = blockIdx.x;                 // 0..127, quarter-molecule
    int b  = bb >> 2;
    int tid = threadIdx.x, wid = tid >> 5, lane = tid & 31;
    if (bb == 0 && tid < BB) g_cnt[tid] = 0;     // reset k4 completion counters
    float c = charge[b];
    int sgn = (c >= 0.0f) ? 0 : 1;
    if (tid < FF) { s_u[tid] = g_u2[sgn][tid]; s_we[tid] = w_e[tid]; }
    __syncthreads();

    float4 uu = ((const float4*)s_u)[lane];
    float4 ww = ((const float4*)s_we)[lane];
    float bk = g_bk2[sgn];
    const float inv_sqrtF = 0.08838834764831845f;
    const float4* ez = (const float4*)e_z;
    int row0 = bb*256 + wid*32;
    float wsum = 0.f;

    #pragma unroll 1
    for (int rr = 0; rr < 32; rr += 2) {
        int n0 = row0 + rr, n1 = n0 + 1;
        float4 va = ez[(size_t)n0*32 + lane];
        float4 vb = ez[(size_t)n1*32 + lane];
        float d1a = va.x*uu.x + va.y*uu.y + va.z*uu.z + va.w*uu.w;
        float d2a = va.x*ww.x + va.y*ww.y + va.z*ww.z + va.w*ww.w;
        float d1b = vb.x*uu.x + vb.y*uu.y + vb.z*uu.z + vb.w*uu.w;
        float d2b = vb.x*ww.x + vb.y*ww.y + vb.z*ww.z + vb.w*ww.w;
        #pragma unroll
        for (int off = 16; off > 0; off >>= 1) {
            d1a += __shfl_xor_sync(0xffffffffu, d1a, off);
            d2a += __shfl_xor_sync(0xffffffffu, d2a, off);
            d1b += __shfl_xor_sync(0xffffffffu, d1b, off);
            d2b += __shfl_xor_sync(0xffffffffu, d2b, off);
        }
        float arga = (d1a + bk) * inv_sqrtF;
        float numa = fmaxf(arga, 0.f) + log1pf(expf(-fabsf(arga)));
        float argb = (d1b + bk) * inv_sqrtF;
        float numb = fmaxf(argb, 0.f) + log1pf(expf(-fabsf(argb)));
        wsum += numa + numb;
        if (lane == 0) {
            g_num[n0] = numa; g_ezwe[n0] = d2a;
            g_num[n1] = numb; g_ezwe[n1] = d2b;
        }
    }
    if (lane == 0) s_ws[wid] = wsum;
    __syncthreads();
    if (tid == 0) {
        float s = 0.f;
        #pragma unroll
        for (int i = 0; i < 8; i++) s += s_ws[i];
        g_numpart[bb] = s;
    }
}

// ---------------- K2: HMMA (mma.sync bf16) res-MLP, register-chained ----------
// smem: sW1 [0,34816) sW2 [34816,69632) s_a 69632 s_v 70144 s_wow 70656; total 71168
#define K2_SMEM 71168
__global__ void __launch_bounds__(256, 2)
k2_mma(const float* __restrict__ charge, const int* __restrict__ z,
       const float* __restrict__ q_tab,
       const float* __restrict__ vp, const float* __restrict__ vm,
       const float* __restrict__ xyz) {
    extern __shared__ char smem[];
    float* s_a   = (float*)(smem + 69632);
    float* s_v   = (float*)(smem + 70144);
    float* s_wow = (float*)(smem + 70656);
    uint32_t sb = smem_u32(smem);

    int tid = threadIdx.x, wid = tid >> 5, lane = tid & 31;
    int m0 = blockIdx.x * 128;
    int b = m0 >> 10;
    float c = charge[b];
    const float* v = (c >= 0.f) ? vp : vm;

    uint4* dst1 = (uint4*)smem;
    uint4* dst2 = (uint4*)(smem + 34816);
    for (int i = tid; i < 2176; i += 256) { dst1[i] = g_W1bf4[i]; dst2[i] = g_W2bf4[i]; }
    if (tid < 128) {
        float tot = g_numpart[b*4] + g_numpart[b*4+1] + g_numpart[b*4+2] + g_numpart[b*4+3];
        s_a[tid]   = c * g_num[m0 + tid] / tot;
        s_v[tid]   = v[tid];
        s_wow[tid] = g_wow[tid];
    }
    __syncthreads();

    int quad = lane >> 2, qt = lane & 3;
    int mrow = wid * 16 + quad;
    float am0 = s_a[mrow], am8 = s_a[mrow + 8];

    int rl = ((lane >> 4) << 3) | (lane & 7);
    uint32_t boff = (uint32_t)(rl * 272 + ((lane >> 3) & 1) * 16);

    uint32_t af[8][4];
    #pragma unroll
    for (int s = 0; s < 8; s++) {
        int k0 = s*16 + qt*2;
        float v0 = s_v[k0], v1 = s_v[k0+1], v8 = s_v[k0+8], v9 = s_v[k0+9];
        af[s][0] = packbf(fsilu(am0*v0), fsilu(am0*v1));
        af[s][1] = packbf(fsilu(am8*v0), fsilu(am8*v1));
        af[s][2] = packbf(fsilu(am0*v8), fsilu(am0*v9));
        af[s][3] = packbf(fsilu(am8*v8), fsilu(am8*v9));
    }

    float acc[16][4];
    #pragma unroll
    for (int nt = 0; nt < 16; nt++)
        #pragma unroll
        for (int i = 0; i < 4; i++) acc[nt][i] = 0.f;
    #pragma unroll
    for (int s = 0; s < 8; s++) {
        #pragma unroll
        for (int np = 0; np < 8; np++) {
            uint32_t b0, b1, b2, b3;
            ldsm_x4(b0, b1, b2, b3, sb + (uint32_t)(np*4352 + s*32) + boff);
            mma16816(acc[2*np],   af[s], b0, b1);
            mma16816(acc[2*np+1], af[s], b2, b3);
        }
    }

    #pragma unroll
    for (int s = 0; s < 8; s++) {
        af[s][0] = packbf(fsilu(acc[2*s][0]),   fsilu(acc[2*s][1]));
        af[s][1] = packbf(fsilu(acc[2*s][2]),   fsilu(acc[2*s][3]));
        af[s][2] = packbf(fsilu(acc[2*s+1][0]), fsilu(acc[2*s+1][1]));
        af[s][3] = packbf(fsilu(acc[2*s+1][2]), fsilu(acc[2*s+1][3]));
    }

    #pragma unroll
    for (int nt = 0; nt < 16; nt++)
        #pragma unroll
        for (int i = 0; i < 4; i++) acc[nt][i] = 0.f;
    #pragma unroll
    for (int s = 0; s < 8; s++) {
        #pragma unroll
        for (int np = 0; np < 8; np++) {
            uint32_t b0, b1, b2, b3;
            ldsm_x4(b0, b1, b2, b3, sb + (uint32_t)(34816 + np*4352 + s*32) + boff);
            mma16816(acc[2*np],   af[s], b0, b1);
            mma16816(acc[2*np+1], af[s], b2, b3);
        }
    }

    float p0 = 0.f, p8 = 0.f;
    #pragma unroll
    for (int nt = 0; nt < 16; nt++) {
        int n = nt*8 + qt*2;
        float vv0 = s_v[n], vv1 = s_v[n+1], w0 = s_wow[n], w1 = s_wow[n+1];
        p0 += fsilu(am0*vv0 + acc[nt][0]) * w0 + fsilu(am0*vv1 + acc[nt][1]) * w1;
        p8 += fsilu(am8*vv0 + acc[nt][2]) * w0 + fsilu(am8*vv1 + acc[nt][3]) * w1;
    }
    p0 += __shfl_xor_sync(0xffffffffu, p0, 1);
    p0 += __shfl_xor_sync(0xffffffffu, p0, 2);
    p8 += __shfl_xor_sync(0xffffffffu, p8, 1);
    p8 += __shfl_xor_sync(0xffffffffu, p8, 2);
    if (qt == 0) {
        int n = m0 + mrow;
        float pr0 = g_ezwe[n]     + p0 + q_tab[z[n]];
        float pr8 = g_ezwe[n + 8] + p8 + q_tab[z[n + 8]];
        size_t b3a = (size_t)n * 3, b3b = (size_t)(n + 8) * 3;
        g_xyzq[n]     = make_float4(xyz[b3a], xyz[b3a+1], xyz[b3a+2], pr0);
        g_xyzq[n + 8] = make_float4(xyz[b3b], xyz[b3b+1], xyz[b3b+2], pr8);
    }
}

// ---------------- K4: correction + O(A^2) Coulomb, min-r2 stash (j-only) ------
#define ROFF2C 14.0625f
#define CAPL 32   // j-iters per lane per tile <= 32 -> stash can never overflow

// switched-correction for one close pair: fs*(rsqrt(r2+1) - rsqrt(r2))
__device__ __forceinline__ float fs_corr(float r2) {
    float rinv = rsqa(r2);
    float r = r2 * rinv;
    float arg = (r - 1.25f) * 0.4f;
    arg = fminf(fmaxf(arg, 1e-7f), 1.f - 1e-7f);
    float num = __expf(__fdividef(-1.f, 1.f - arg));
    float den = __expf(__fdividef(-1.f, arg));
    float fs  = __fdividef(num, num + den);
    return fs * (rsqa(r2 + 1.f) - rinv);
}

// flush: re-evaluate the 8 pairs of each stashed j against the current tile
__device__ __forceinline__ float flush8(const float4* sp, const uint32_t* wst, int lane,
                                        int cnt, const float* xi, const float* yi,
                                        const float* zi, const float* qi) {
    float e = 0.f;
    for (int s = 0; s < cnt; s++) {
        int j = (int)wst[s*32 + lane];
        float4 pj = sp[j];
        #pragma unroll
        for (int r = 0; r < 8; r++) {
            float dx = xi[r]-pj.x, dy = yi[r]-pj.y, dz = zi[r]-pj.z;
            float r2 = dx*dx + dy*dy + dz*dz;
            if (r2 < ROFF2C) e += qi[r] * pj.w * fs_corr(r2);
        }
    }
    return e;
}

__global__ void __launch_bounds__(128, 4)
k4_pair(const float* __restrict__ charge, float* __restrict__ out) {
    int b = blockIdx.y, t = blockIdx.x, tid = threadIdx.x;
    __shared__ float4 sp[AA];
    __shared__ uint32_t s_stash[4*(CAPL+1)*32];  // [wid][entry][lane], row CAPL = dump
    __shared__ float s_red[128];
    float psum = 0.f;
    // packed prologue: one LDG.128 per atom
    #pragma unroll
    for (int it = 0; it < 8; it++) {
        int a = tid + it*128;
        float4 v = g_xyzq[b*AA + a];
        sp[a] = v;
        psum += v.w;
    }
    s_red[tid] = psum; __syncthreads();
    for (int off = 64; off > 0; off >>= 1) {
        if (tid < off) s_red[tid] += s_red[tid + off];
        __syncthreads();
    }
    float corr = (charge[b] - s_red[0]) * (1.0f / AA);
    __syncthreads();
    for (int a = tid; a < AA; a += 128) sp[a].w += corr;
    __syncthreads();

    int wid = tid >> 5, lane = tid & 31;
    int wglob = t*4 + wid;                 // 0..63
    uint32_t* wst = s_stash + wid*((CAPL+1)*32);
    float e0 = 0.f;

    #pragma unroll 1
    for (int tt = 0; tt < 2; tt++) {
        int base = (tt == 0) ? (wglob * 8) : (1016 - wglob * 8);
        float xi[8], yi[8], zi[8], qi[8];
        #pragma unroll
        for (int r = 0; r < 8; r++) {
            float4 p = sp[base + r];
            xi[r] = p.x; yi[r] = p.y; zi[r] = p.z; qi[r] = p.w;
        }
        float facc[8];
        #pragma unroll
        for (int r = 0; r < 8; r++) facc[r] = 0.f;

        // intra-tile corner (28 pairs): inline switched formula, predicated
        {
            bool lv = (lane >= 1) && (lane < 8);
            float4 pj = sp[base + (lv ? lane : 0)];
            #pragma unroll
            for (int r = 0; r < 7; r++) {
                bool val = lv && (lane > r);
                float dx = xi[r]-pj.x, dy = yi[r]-pj.y, dz = zi[r]-pj.z;
                float r2 = dx*dx + dy*dy + dz*dz;
                float r2s = val ? r2 : 1.0f;
                float qq  = val ? qi[r]*pj.w : 0.0f;
                e0 = fmaf(qq, rsqa(r2s) + ((r2s < ROFF2C) ? fs_corr(r2s) : 0.f), e0);
            }
        }

        // main sweep: lanes stream distinct j; ONE branch-free stash decision per j
        int cnt = 0;
        for (int j = base + 8 + lane; j < AA; j += 32) {
            float4 pj = sp[j];
            float m = 1.0e30f;
            #pragma unroll
            for (int r = 0; r < 8; r++) {
                float dx = xi[r]-pj.x, dy = yi[r]-pj.y, dz = zi[r]-pj.z;
                float r2 = dx*dx + dy*dy + dz*dz;
                m = fminf(m, r2);
                facc[r] = fmaf(pj.w, rsqa(r2), facc[r]);
            }
            bool close = (m < ROFF2C);
            wst[(close ? cnt : CAPL)*32 + lane] = (uint32_t)j;   // dump row when far
            cnt += (int)close;
        }
        e0 += flush8(sp, wst, lane, cnt, xi, yi, zi, qi);
        #pragma unroll
        for (int r = 0; r < 8; r++) e0 = fmaf(qi[r], facc[r], e0);
    }

    s_red[tid] = e0; __syncthreads();
    for (int off = 64; off > 0; off >>= 1) {
        if (tid < off) s_red[tid] += s_red[tid + off];
        __syncthreads();
    }
    if (tid == 0) {
        g_partial[b*16 + t] = s_red[0];
        __threadfence();
        int done = atomicAdd(&g_cnt[b], 1);
        if (done == 15) {   // last block of this molecule: deterministic fixed-order sum
            volatile float* gp = g_partial;
            float s = 0.f;
            #pragma unroll
            for (int q = 0; q < 16; q++) s += gp[b*16 + q];
            out[b] = 332.0636f * s;
        }
    }
}

extern "C" void kernel_launch(void* const* d_in, const int* in_sizes, int n_in,
                              void* d_out, int out_size) {
    const float* e_z     = (const float*)d_in[0];
    const float* charge  = (const float*)d_in[1];
    const float* xyz     = (const float*)d_in[2];
    const float* W_lin   = (const float*)d_in[3];
    const float* b_lin   = (const float*)d_in[4];
    const float* k_plus  = (const float*)d_in[5];
    const float* k_minus = (const float*)d_in[6];
    const float* v_plus  = (const float*)d_in[7];
    const float* v_minus = (const float*)d_in[8];
    const float* Wr1     = (const float*)d_in[9];
    const float* Wr2     = (const float*)d_in[10];
    const float* Wout    = (const float*)d_in[11];
    const float* w_e     = (const float*)d_in[12];
    const float* q_tab   = (const float*)d_in[13];
    const int*   z       = (const int*)d_in[14];
    float* out = (float*)d_out;

    cudaFuncSetAttribute(k2_mma, cudaFuncAttributeMaxDynamicSharedMemorySize, K2_SMEM);

    k0f<<<193, 256>>>(Wr1, Wr2, W_lin, b_lin, k_plus, k_minus, Wout, w_e);
    k1_fused<<<NN/256, 256>>>(e_z, charge, w_e);
    k2_mma<<<NN/128, 256, K2_SMEM>>>(charge, z, q_tab, v_plus, v_minus, xyz);
    dim3 g4(16, BB);
    k4_pair<<<g4, 128>>>(charge, out);
}

// round 14
// speedup vs baseline: 1.2096x; 1.2096x over previous
#include <cuda_runtime.h>
#include <cuda_bf16.h>
#include <math.h>
#include <cstdint>

#define BB 32
#define AA 1024
#define FF 128
#define NN (BB*AA)

// ================= scratch =================
__device__ float g_u2[2][FF];
__device__ float g_bk2[2];
__device__ float g_wow[FF];
__device__ float g_num[NN];
__device__ float g_numpart[NN/256];
__device__ float g_ezwe[NN];
__device__ float4 g_xyzq[NN];       // packed (x, y, z, pred_q) written by k2
__device__ float g_partial[BB*16];
__device__ int   g_cnt[BB];
// W1^T / W2^T as bf16, layout Wt[n][k], row stride 136 (272 B): 128*136*2 = 34816 B each
__device__ uint4 g_W1bf4[2176];
__device__ uint4 g_W2bf4[2176];

__device__ __forceinline__ float tanha(float x) {
    float r;
    asm("tanh.approx.f32 %0, %1;" : "=f"(r) : "f"(x));
    return r;
}
__device__ __forceinline__ float fsilu(float x) {   // x*sigmoid(x) = 0.5x(1+tanh(x/2))
    float h = 0.5f * x;
    return fmaf(h, tanha(h), h);
}
__device__ __forceinline__ float rsqa(float x) {    // exactly one MUFU.RSQ
    float r;
    asm("rsqrt.approx.f32 %0, %1;" : "=f"(r) : "f"(x));
    return r;
}
__device__ __forceinline__ uint32_t packbf(float lo, float hi) {
    uint32_t r;
    asm("cvt.rn.satfinite.bf16x2.f32 %0, %1, %2;" : "=r"(r) : "f"(hi), "f"(lo));
    return r;
}
__device__ __forceinline__ uint32_t smem_u32(const void* p) {
    uint32_t a;
    asm("{ .reg .u64 t; cvta.to.shared.u64 t, %1; cvt.u32.u64 %0, t; }" : "=r"(a) : "l"(p));
    return a;
}
__device__ __forceinline__ void ldsm_x4(uint32_t& r0, uint32_t& r1, uint32_t& r2, uint32_t& r3,
                                        uint32_t addr) {
    asm volatile("ldmatrix.sync.aligned.m8n8.x4.shared.b16 {%0,%1,%2,%3}, [%4];"
                 : "=r"(r0), "=r"(r1), "=r"(r2), "=r"(r3) : "r"(addr));
}
__device__ __forceinline__ void mma16816(float* d, const uint32_t* a, uint32_t b0, uint32_t b1) {
    asm volatile("mma.sync.aligned.m16n8k16.row.col.f32.bf16.bf16.f32 "
                 "{%0,%1,%2,%3}, {%4,%5,%6,%7}, {%8,%9}, {%0,%1,%2,%3};"
                 : "+f"(d[0]), "+f"(d[1]), "+f"(d[2]), "+f"(d[3])
                 : "r"(a[0]), "r"(a[1]), "r"(a[2]), "r"(a[3]), "r"(b0), "r"(b1));
}

// ---------------- K0f: projected vectors only (weight convert moved to k1) ----
__global__ void k0f(const float* __restrict__ W_lin, const float* __restrict__ b_lin,
                    const float* __restrict__ kp, const float* __restrict__ km,
                    const float* __restrict__ Wout, const float* __restrict__ w_e) {
    int blk = blockIdx.x, tid = threadIdx.x;
    __shared__ float r0[256], r1[256], r2[256];
    if (blk < 128) {
        int g = blk;
        float a0 = 0.f, a1 = 0.f, a2 = 0.f;
        if (tid < 128) {
            float w = W_lin[g*FF + tid];
            a0 = w * kp[tid];
            a1 = w * km[tid];
            a2 = Wout[g*FF + tid] * w_e[tid];
        }
        r0[tid] = a0; r1[tid] = a1; r2[tid] = a2;
        __syncthreads();
        for (int off = 128; off > 0; off >>= 1) {
            if (tid < off) { r0[tid] += r0[tid+off]; r1[tid] += r1[tid+off]; r2[tid] += r2[tid+off]; }
            __syncthreads();
        }
        if (tid == 0) { g_u2[0][g] = r0[0]; g_u2[1][g] = r1[0]; g_wow[g] = r2[0]; }
        return;
    }
    float a0 = 0.f, a1 = 0.f;
    if (tid < 128) { float bl = b_lin[tid]; a0 = bl * kp[tid]; a1 = bl * km[tid]; }
    r0[tid] = a0; r1[tid] = a1;
    __syncthreads();
    for (int off = 128; off > 0; off >>= 1) {
        if (tid < off) { r0[tid] += r0[tid+off]; r1[tid] += r1[tid+off]; }
        __syncthreads();
    }
    if (tid == 0) { g_bk2[0] = r0[0]; g_bk2[1] = r1[0]; }
}

// ---------------- K1: row dots (blocks 0-127) + weight convert (128-191) -----
__global__ void k1_fused(const float* __restrict__ e_z, const float* __restrict__ charge,
                         const float* __restrict__ w_e,
                         const float* __restrict__ W1, const float* __restrict__ W2) {
    int bb = blockIdx.x;
    int tid = threadIdx.x;
    if (bb >= 128) {                     // weight-convert blocks (independent of k0f)
        int i = (bb - 128) * 256 + tid;  // 0..16383
        int k = i >> 7, n = i & 127;
        int off = n*136 + k;
        ((__nv_bfloat16*)g_W1bf4)[off] = __float2bfloat16(W1[k*FF + n]);
        ((__nv_bfloat16*)g_W2bf4)[off] = __float2bfloat16(W2[k*FF + n]);
        return;
    }
    __shared__ float s_u[FF];
    __shared__ float s_we[FF];
    __shared__ float s_ws[8];
    int b  = bb >> 2;
    int wid = tid >> 5, lane = tid & 31;
    if (bb == 0 && tid < BB) g_cnt[tid] = 0;     // reset k4 completion counters
    float c = charge[b];
    int sgn = (c >= 0.0f) ? 0 : 1;
    if (tid < FF) { s_u[tid] = g_u2[sgn][tid]; s_we[tid] = w_e[tid]; }
    __syncthreads();

    float4 uu = ((const float4*)s_u)[lane];
    float4 ww = ((const float4*)s_we)[lane];
    float bk = g_bk2[sgn];
    const float inv_sqrtF = 0.08838834764831845f;
    const float4* ez = (const float4*)e_z;
    int row0 = bb*256 + wid*32;
    float wsum = 0.f;

    #pragma unroll 1
    for (int rr = 0; rr < 32; rr += 2) {
        int n0 = row0 + rr, n1 = n0 + 1;
        float4 va = ez[(size_t)n0*32 + lane];
        float4 vb = ez[(size_t)n1*32 + lane];
        float d1a = va.x*uu.x + va.y*uu.y + va.z*uu.z + va.w*uu.w;
        float d2a = va.x*ww.x + va.y*ww.y + va.z*ww.z + va.w*ww.w;
        float d1b = vb.x*uu.x + vb.y*uu.y + vb.z*uu.z + vb.w*uu.w;
        float d2b = vb.x*ww.x + vb.y*ww.y + vb.z*ww.z + vb.w*ww.w;
        #pragma unroll
        for (int off = 16; off > 0; off >>= 1) {
            d1a += __shfl_xor_sync(0xffffffffu, d1a, off);
            d2a += __shfl_xor_sync(0xffffffffu, d2a, off);
            d1b += __shfl_xor_sync(0xffffffffu, d1b, off);
            d2b += __shfl_xor_sync(0xffffffffu, d2b, off);
        }
        float arga = (d1a + bk) * inv_sqrtF;
        float numa = fmaxf(arga, 0.f) + log1pf(expf(-fabsf(arga)));
        float argb = (d1b + bk) * inv_sqrtF;
        float numb = fmaxf(argb, 0.f) + log1pf(expf(-fabsf(argb)));
        wsum += numa + numb;
        if (lane == 0) {
            g_num[n0] = numa; g_ezwe[n0] = d2a;
            g_num[n1] = numb; g_ezwe[n1] = d2b;
        }
    }
    if (lane == 0) s_ws[wid] = wsum;
    __syncthreads();
    if (tid == 0) {
        float s = 0.f;
        #pragma unroll
        for (int i = 0; i < 8; i++) s += s_ws[i];
        g_numpart[bb] = s;
    }
}

// ---------------- K2: HMMA res-MLP, register-chained, halved accumulators -----
// smem: sW1 [0,34816) sW2 [34816,69632) s_a 69632 s_v 70144 s_wow 70656; total 71168
#define K2_SMEM 71168
__global__ void __launch_bounds__(256, 2)
k2_mma(const float* __restrict__ charge, const int* __restrict__ z,
       const float* __restrict__ q_tab,
       const float* __restrict__ vp, const float* __restrict__ vm,
       const float* __restrict__ xyz) {
    extern __shared__ char smem[];
    float* s_a   = (float*)(smem + 69632);
    float* s_v   = (float*)(smem + 70144);
    float* s_wow = (float*)(smem + 70656);
    uint32_t sb = smem_u32(smem);

    int tid = threadIdx.x, wid = tid >> 5, lane = tid & 31;
    int m0 = blockIdx.x * 128;
    int b = m0 >> 10;
    float c = charge[b];
    const float* v = (c >= 0.f) ? vp : vm;

    uint4* dst1 = (uint4*)smem;
    uint4* dst2 = (uint4*)(smem + 34816);
    for (int i = tid; i < 2176; i += 256) { dst1[i] = g_W1bf4[i]; dst2[i] = g_W2bf4[i]; }
    if (tid < 128) {
        float tot = g_numpart[b*4] + g_numpart[b*4+1] + g_numpart[b*4+2] + g_numpart[b*4+3];
        s_a[tid]   = c * g_num[m0 + tid] / tot;
        s_v[tid]   = v[tid];
        s_wow[tid] = g_wow[tid];
    }
    __syncthreads();

    int quad = lane >> 2, qt = lane & 3;
    int mrow = wid * 16 + quad;
    float am0 = s_a[mrow], am8 = s_a[mrow + 8];

    int rl = ((lane >> 4) << 3) | (lane & 7);
    uint32_t boff = (uint32_t)(rl * 272 + ((lane >> 3) & 1) * 16);

    // GEMM1 A fragments: X = silu(a*v), analytic
    uint32_t af[8][4];
    #pragma unroll
    for (int s = 0; s < 8; s++) {
        int k0 = s*16 + qt*2;
        float v0 = s_v[k0], v1 = s_v[k0+1], v8 = s_v[k0+8], v9 = s_v[k0+9];
        af[s][0] = packbf(fsilu(am0*v0), fsilu(am0*v1));
        af[s][1] = packbf(fsilu(am8*v0), fsilu(am8*v1));
        af[s][2] = packbf(fsilu(am0*v8), fsilu(am0*v9));
        af[s][3] = packbf(fsilu(am8*v8), fsilu(am8*v9));
    }

    // ---- GEMM1 in two n-halves; acc is 8x4 (32 regs) ----
    uint32_t af2[8][4];
    float acc[8][4];
    #pragma unroll
    for (int h = 0; h < 2; h++) {
        #pragma unroll
        for (int l = 0; l < 8; l++)
            #pragma unroll
            for (int i = 0; i < 4; i++) acc[l][i] = 0.f;
        #pragma unroll
        for (int s = 0; s < 8; s++) {
            #pragma unroll
            for (int npl = 0; npl < 4; npl++) {
                int np = h*4 + npl;
                uint32_t b0, b1, b2, b3;
                ldsm_x4(b0, b1, b2, b3, sb + (uint32_t)(np*4352 + s*32) + boff);
                mma16816(acc[2*npl],   af[s], b0, b1);
                mma16816(acc[2*npl+1], af[s], b2, b3);
            }
        }
        // chain: af2[h*4+ss] = silu(h1) fragments from local acc
        #pragma unroll
        for (int ss = 0; ss < 4; ss++) {
            int s2 = h*4 + ss;
            af2[s2][0] = packbf(fsilu(acc[2*ss][0]),   fsilu(acc[2*ss][1]));
            af2[s2][1] = packbf(fsilu(acc[2*ss][2]),   fsilu(acc[2*ss][3]));
            af2[s2][2] = packbf(fsilu(acc[2*ss+1][0]), fsilu(acc[2*ss+1][1]));
            af2[s2][3] = packbf(fsilu(acc[2*ss+1][2]), fsilu(acc[2*ss+1][3]));
        }
    }

    // ---- GEMM2 in two n-halves + fused epilogue ----
    float p0 = 0.f, p8 = 0.f;
    #pragma unroll
    for (int h = 0; h < 2; h++) {
        #pragma unroll
        for (int l = 0; l < 8; l++)
            #pragma unroll
            for (int i = 0; i < 4; i++) acc[l][i] = 0.f;
        #pragma unroll
        for (int s = 0; s < 8; s++) {
            #pragma unroll
            for (int npl = 0; npl < 4; npl++) {
                int np = h*4 + npl;
                uint32_t b0, b1, b2, b3;
                ldsm_x4(b0, b1, b2, b3, sb + (uint32_t)(34816 + np*4352 + s*32) + boff);
                mma16816(acc[2*npl],   af2[s], b0, b1);
                mma16816(acc[2*npl+1], af2[s], b2, b3);
            }
        }
        #pragma unroll
        for (int ntl = 0; ntl < 8; ntl++) {
            int n = (h*8 + ntl)*8 + qt*2;
            float vv0 = s_v[n], vv1 = s_v[n+1], w0 = s_wow[n], w1 = s_wow[n+1];
            p0 += fsilu(am0*vv0 + acc[ntl][0]) * w0 + fsilu(am0*vv1 + acc[ntl][1]) * w1;
            p8 += fsilu(am8*vv0 + acc[ntl][2]) * w0 + fsilu(am8*vv1 + acc[ntl][3]) * w1;
        }
    }

    p0 += __shfl_xor_sync(0xffffffffu, p0, 1);
    p0 += __shfl_xor_sync(0xffffffffu, p0, 2);
    p8 += __shfl_xor_sync(0xffffffffu, p8, 1);
    p8 += __shfl_xor_sync(0xffffffffu, p8, 2);
    if (qt == 0) {
        int n = m0 + mrow;
        float pr0 = g_ezwe[n]     + p0 + q_tab[z[n]];
        float pr8 = g_ezwe[n + 8] + p8 + q_tab[z[n + 8]];
        size_t b3a = (size_t)n * 3, b3b = (size_t)(n + 8) * 3;
        g_xyzq[n]     = make_float4(xyz[b3a], xyz[b3a+1], xyz[b3a+2], pr0);
        g_xyzq[n + 8] = make_float4(xyz[b3b], xyz[b3b+1], xyz[b3b+2], pr8);
    }
}

// ---------------- K4: correction + O(A^2) Coulomb (R12 exact) -----------------
#define ROFF2C 14.0625f
#define CAPL 24   // stash entries per lane

__device__ __forceinline__ float flush_smem(const float4* sp, uint32_t* wstash,
                                            int lane, int& scnt) {
    float e = 0.f;
    for (int s = 0; s < scnt; s++) {
        uint32_t vv = wstash[s*32 + lane];
        int j = vv >> 10, i = vv & 1023;
        float4 pi = sp[i], pj = sp[j];
        float dx = pi.x-pj.x, dy = pi.y-pj.y, dz = pi.z-pj.z;
        float r2 = dx*dx + dy*dy + dz*dz;
        float rinv = rsqa(r2);
        float r = r2 * rinv;
        float arg = (r - 1.25f) * 0.4f;
        arg = fminf(fmaxf(arg, 1e-7f), 1.f - 1e-7f);
        float num = __expf(__fdividef(-1.f, 1.f - arg));
        float den = __expf(__fdividef(-1.f, arg));
        float fs  = __fdividef(num, num + den);
        e += pi.w * pj.w * fs * (rsqa(r2 + 1.f) - rinv);
    }
    scnt = 0;
    return e;
}

__global__ void __launch_bounds__(128, 4)
k4_pair(const float* __restrict__ charge, float* __restrict__ out) {
    int b = blockIdx.y, t = blockIdx.x, tid = threadIdx.x;
    __shared__ float4 sp[AA];
    __shared__ uint32_t s_stash[4*32*CAPL];      // [wid][entry][lane]
    __shared__ float s_red[128];
    float psum = 0.f;
    // packed prologue: one LDG.128 per atom
    #pragma unroll
    for (int it = 0; it < 8; it++) {
        int a = tid + it*128;
        float4 v = g_xyzq[b*AA + a];
        sp[a] = v;
        psum += v.w;
    }
    s_red[tid] = psum; __syncthreads();
    for (int off = 64; off > 0; off >>= 1) {
        if (tid < off) s_red[tid] += s_red[tid + off];
        __syncthreads();
    }
    float corr = (charge[b] - s_red[0]) * (1.0f / AA);
    __syncthreads();
    for (int a = tid; a < AA; a += 128) sp[a].w += corr;
    __syncthreads();

    int wid = tid >> 5, lane = tid & 31;
    int wglob = t*4 + wid;                 // 0..63
    uint32_t* wstash = s_stash + wid*(32*CAPL);
    int scnt = 0;
    float e0 = 0.f;

    #pragma unroll 1
    for (int tt = 0; tt < 2; tt++) {
        int base = (tt == 0) ? (wglob * 8) : (1016 - wglob * 8);
        float xi[8], yi[8], zi[8], qi[8];
        #pragma unroll
        for (int r = 0; r < 8; r++) {
            float4 p = sp[base + r];
            xi[r] = p.x; yi[r] = p.y; zi[r] = p.z; qi[r] = p.w;
        }
        float facc[8];
        #pragma unroll
        for (int r = 0; r < 8; r++) facc[r] = 0.f;

        // intra-tile corner (28 pairs)
        {
            bool lv = (lane >= 1) && (lane < 8);
            int jc = base + (lv ? lane : 0);
            float4 pj = sp[jc];
            #pragma unroll
            for (int r = 0; r < 8; r++) {
                bool val = lv && (lane > r);
                float dx = xi[r]-pj.x, dy = yi[r]-pj.y, dz = zi[r]-pj.z;
                float r2 = dx*dx + dy*dy + dz*dz;
                float r2s = val ? r2 : 1.0f;
                float qv  = val ? pj.w : 0.0f;
                facc[r] = fmaf(qv, rsqa(r2s), facc[r]);
                if (val && r2 < ROFF2C) { wstash[scnt*32 + lane] = ((uint32_t)jc << 10) | (uint32_t)(base + r); scnt++; }
            }
        }
        // main sweep: lanes stream distinct j, 8-row register tile, factored acc
        for (int j = base + 8 + lane; j < AA; j += 32) {
            float4 pj = sp[j];
            uint32_t jp = ((uint32_t)j << 10) + (uint32_t)base;
            #pragma unroll
            for (int r = 0; r < 8; r++) {
                float dx = xi[r]-pj.x, dy = yi[r]-pj.y, dz = zi[r]-pj.z;
                float r2 = dx*dx + dy*dy + dz*dz;
                facc[r] = fmaf(pj.w, rsqa(r2), facc[r]);
                if (r2 < ROFF2C) { wstash[scnt*32 + lane] = jp + (uint32_t)r; scnt++; }
            }
            if (scnt >= CAPL - 8) e0 += flush_smem(sp, wstash, lane, scnt);  // ~never taken
        }
        #pragma unroll
        for (int r = 0; r < 8; r++) e0 = fmaf(qi[r], facc[r], e0);
    }
    e0 += flush_smem(sp, wstash, lane, scnt);

    s_red[tid] = e0; __syncthreads();
    for (int off = 64; off > 0; off >>= 1) {
        if (tid < off) s_red[tid] += s_red[tid + off];
        __syncthreads();
    }
    if (tid == 0) {
        g_partial[b*16 + t] = s_red[0];
        __threadfence();
        int done = atomicAdd(&g_cnt[b], 1);
        if (done == 15) {   // last block of this molecule: deterministic fixed-order sum
            volatile float* gp = g_partial;
            float s = 0.f;
            #pragma unroll
            for (int q = 0; q < 16; q++) s += gp[b*16 + q];
            out[b] = 332.0636f * s;
        }
    }
}

extern "C" void kernel_launch(void* const* d_in, const int* in_sizes, int n_in,
                              void* d_out, int out_size) {
    const float* e_z     = (const float*)d_in[0];
    const float* charge  = (const float*)d_in[1];
    const float* xyz     = (const float*)d_in[2];
    const float* W_lin   = (const float*)d_in[3];
    const float* b_lin   = (const float*)d_in[4];
    const float* k_plus  = (const float*)d_in[5];
    const float* k_minus = (const float*)d_in[6];
    const float* v_plus  = (const float*)d_in[7];
    const float* v_minus = (const float*)d_in[8];
    const float* Wr1     = (const float*)d_in[9];
    const float* Wr2     = (const float*)d_in[10];
    const float* Wout    = (const float*)d_in[11];
    const float* w_e     = (const float*)d_in[12];
    const float* q_tab   = (const float*)d_in[13];
    const int*   z       = (const int*)d_in[14];
    float* out = (float*)d_out;

    cudaFuncSetAttribute(k2_mma, cudaFuncAttributeMaxDynamicSharedMemorySize, K2_SMEM);

    k0f<<<129, 256>>>(W_lin, b_lin, k_plus, k_minus, Wout, w_e);
    k1_fused<<<192, 256>>>(e_z, charge, w_e, Wr1, Wr2);
    k2_mma<<<NN/128, 256, K2_SMEM>>>(charge, z, q_tab, v_plus, v_minus, xyz);
    dim3 g4(16, BB);
    k4_pair<<<g4, 128>>>(charge, out);
}